// round 3
// baseline (speedup 1.0000x reference)
#include <cuda_runtime.h>
#include <cstdint>

// ---------------------------------------------------------------------------
// CapsNet forward, fused.
//  * routing never updates logits -> c uniform -> s[b,d,i] = mean_n dig[b,n,d]
//  * conv1 channel c = n*8+d; conv2 (kD=1) reduces over n per fixed d
//  * block = (d, batch-triple): 3 batches share every W2 stage (x3 amortize),
//    W2 double-buffered via cp.async (no exposed LDG latency).
//  * fp32 math via packed fma.rn.f32x2 (FFMA2), operands pre-paired.
// ---------------------------------------------------------------------------

typedef unsigned long long ull;

#define NTHR 576            // 18 warps: 3 groups x 6 row-warps
#define NGRP 3

// smem layout (floats)
#define OFF_X    0              // 3 x 784 images (reused as RED at end)
#define OFF_WA   2352           // 5184: W1, then W2[odd ci2]
#define OFF_WB   7536           // 5184: W2[even ci2]
#define OFF_C1   12720          // 3 x 16 x 804 conv1 out, ci-pair interleaved
#define C1_STRIDE 804
#define C1_SLAB  (16 * C1_STRIDE)
#define SMEM_FLOATS (12720 + 3 * C1_SLAB)    // 51312 -> 205.2 KB
#define SMEM_BYTES  (SMEM_FLOATS * 4)

__device__ float g_W1p[8][5184];    // [d][(tap*32+n)*2 + {0,1}] duplicated pair
__device__ float g_W2p[16][5184];   // [ci2][(tap*32+co)*2 + {even,odd}]
__device__ float g_partial[512 * 8 * 16];
__device__ float g_WbSum[16];
__device__ float g_WSum[160];

__device__ __forceinline__ ull ffma2(ull a, ull b, ull c) {
    ull d;
    asm("fma.rn.f32x2 %0, %1, %2, %3;" : "=l"(d) : "l"(a), "l"(b), "l"(c));
    return d;
}
__device__ __forceinline__ float lo32(ull v) { return __uint_as_float((unsigned)v); }
__device__ __forceinline__ float hi32(ull v) { return __uint_as_float((unsigned)(v >> 32)); }
__device__ __forceinline__ ull packf(unsigned lo, unsigned hi) {
    return ((ull)hi << 32) | lo;
}
__device__ __forceinline__ uint32_t smem_u32(const void* p) {
    return (uint32_t)__cvta_generic_to_shared(p);
}
__device__ __forceinline__ void cp_async16(uint32_t dst, const void* src) {
    asm volatile("cp.async.cg.shared.global [%0], [%1], 16;" :: "r"(dst), "l"(src));
}
__device__ __forceinline__ void cp_commit() {
    asm volatile("cp.async.commit_group;");
}
template <int N>
__device__ __forceinline__ void cp_wait() {
    asm volatile("cp.async.wait_group %0;" :: "n"(N));
}

// ---------------------------------------------------------------------------
__global__ void caps_prepW(const float* __restrict__ w1,
                           const float* __restrict__ w2) {
    int t = blockIdx.x * blockDim.x + threadIdx.x;
    if (t < 8 * 2592) {
        int d = t / 2592, i = t % 2592;
        int n = i / 81, tap = i % 81;
        float w = w1[(n * 8 + d) * 81 + tap];
        g_W1p[d][(tap * 32 + n) * 2 + 0] = w;
        g_W1p[d][(tap * 32 + n) * 2 + 1] = w;
    }
    if (t < 16 * 2592) {
        int c2 = t / 2592, i = t % 2592;
        int co = i / 81, tap = i % 81;
        g_W2p[c2][(tap * 32 + co) * 2 + 0] = w2[co * 2592 + (2 * c2) * 81 + tap];
        g_W2p[c2][(tap * 32 + co) * 2 + 1] = w2[co * 2592 + (2 * c2 + 1) * 81 + tap];
    }
}

__global__ void caps_prepS(const float* __restrict__ digWb,
                           const float* __restrict__ outw) {
    __shared__ float acc[256];
    int t = threadIdx.x;
    int e = t & 15, grp = t >> 4;
    float s = 0.f;
    for (int n = grp; n < 1152; n += 16) s += digWb[n * 16 + e];
    acc[t] = s;
    __syncthreads();
    if (t < 16) {
        float tot = 0.f;
        #pragma unroll
        for (int g = 0; g < 16; g++) tot += acc[g * 16 + t];
        g_WbSum[t] = tot;
    }
    if (t < 160) {
        int o = t / 16, k = t & 15;
        float w = 0.f;
        #pragma unroll
        for (int i = 0; i < 10; i++) w += outw[(o * 10 + i) * 16 + k];
        g_WSum[t] = w;
    }
}

// ---------------------------------------------------------------------------
// fused: grid (8 d, 171 batch-triples), 576 threads.
// warp w: group g = w/6 (batch), row-warp r = w%6.
// ---------------------------------------------------------------------------
__global__ void __launch_bounds__(NTHR, 1)
caps_fused(const float* __restrict__ gx,  const float* __restrict__ gb1,
           const float* __restrict__ gpb, const float* __restrict__ gdW)
{
    extern __shared__ float sm[];
    float* Xall = sm + OFF_X;
    float* WA   = sm + OFF_WA;
    float* WB   = sm + OFF_WB;
    float* C1a  = sm + OFF_C1;

    const int d    = blockIdx.x;
    const int bq   = blockIdx.y;
    const int tid  = threadIdx.x;
    const int lane = tid & 31;
    const int warp = tid >> 5;
    const int g    = warp / 6;         // batch group 0..2
    const int r    = warp % 6;         // row warp 0..5

    const int bb = min(bq * 3 + g, 511);   // clamped (dup writes identical)

    float* X  = Xall + g * 784;
    float* C1 = C1a  + g * C1_SLAB;

    // ---- stage: W1 -> WA (cp.async g0), W2[0] -> WB (g1), images (LDG) ----
    {
        const float4* ws = reinterpret_cast<const float4*>(g_W1p[d]);
        for (int i = tid; i < 1296; i += NTHR)
            cp_async16(smem_u32(WA + 4 * i), ws + i);
        cp_commit();
        const float4* w2s = reinterpret_cast<const float4*>(g_W2p[0]);
        for (int i = tid; i < 1296; i += NTHR)
            cp_async16(smem_u32(WB + 4 * i), w2s + i);
        cp_commit();
        // images: 3 x 196 float4
        float4* xd = reinterpret_cast<float4*>(Xall);
        for (int i = tid; i < 588; i += NTHR) {
            int gg = i / 196, idx = i % 196;
            int bsel = min(bq * 3 + gg, 511);
            xd[i] = reinterpret_cast<const float4*>(gx + bsel * 784)[idx];
        }
    }
    cp_wait<1>();        // W1 complete (W2[0] may still be in flight)
    __syncthreads();

    const float b1 = gb1[lane * 8 + d];

    // ---- conv1: 9x9 VALID, 28x28 -> 20x20, channel = lane ------------------
    for (int y = r; y < 20; y += 6) {
        ull accP[10];
        #pragma unroll
        for (int xp = 0; xp < 10; xp++) accP[xp] = 0ull;

        #pragma unroll 1
        for (int ky = 0; ky < 9; ky++) {
            const float* row = X + (y + ky) * 28;
            ull P[27];
            #pragma unroll
            for (int i = 0; i < 14; i++) P[2 * i] = *(const ull*)(row + 2 * i);
            #pragma unroll
            for (int i = 0; i < 13; i++)
                P[2 * i + 1] = packf((unsigned)(P[2 * i] >> 32),
                                     (unsigned)P[2 * i + 2]);
            #pragma unroll
            for (int kx = 0; kx < 9; kx++) {
                ull wp = *(const ull*)(WA + ((ky * 9 + kx) * 32 + lane) * 2);
                #pragma unroll
                for (int xp = 0; xp < 10; xp++)
                    accP[xp] = ffma2(P[2 * xp + kx], wp, accP[xp]);
            }
        }
        const int cbase = (lane >> 1) * C1_STRIDE + (lane & 1);
        #pragma unroll
        for (int xp = 0; xp < 10; xp++) {
            float v0 = fmaxf(lo32(accP[xp]) + b1, 0.f);
            float v1 = fmaxf(hi32(accP[xp]) + b1, 0.f);
            C1[cbase + (y * 20 + 2 * xp) * 2]     = v0;
            C1[cbase + (y * 20 + 2 * xp + 1) * 2] = v1;
        }
    }
    __syncthreads();     // conv1 done everywhere; WA free for W2[1]

    // ---- conv2: 32ci -> 32co, 9x9 stride 2 -> 6x6; double-buffered W2 ------
    const float pb = gpb[lane];
    ull acc2[6];
    #pragma unroll
    for (int x = 0; x < 6; x++) acc2[x] = 0ull;

    #pragma unroll 1
    for (int ci2 = 0; ci2 < 16; ci2++) {
        float* cur = (ci2 & 1) ? WA : WB;
        if (ci2 + 1 < 16) {
            float* nxt = (ci2 & 1) ? WB : WA;
            const float4* ws = reinterpret_cast<const float4*>(g_W2p[ci2 + 1]);
            for (int i = tid; i < 1296; i += NTHR)
                cp_async16(smem_u32(nxt + 4 * i), ws + i);
            cp_commit();
            cp_wait<1>();   // cur's group complete, next stays in flight
        } else {
            cp_wait<0>();
        }
        __syncthreads();

        const float* cb = C1 + ci2 * C1_STRIDE;
        #pragma unroll 1
        for (int ky = 0; ky < 9; ky++) {
            const float* rp = cb + (2 * r + ky) * 40;
            ull P[20];
            #pragma unroll
            for (int c4 = 0; c4 < 10; c4++) {
                ulonglong2 q = *(const ulonglong2*)(rp + c4 * 4);
                P[2 * c4]     = q.x;
                P[2 * c4 + 1] = q.y;
            }
            #pragma unroll
            for (int kx = 0; kx < 9; kx++) {
                ull wp = *(const ull*)(cur + ((ky * 9 + kx) * 32 + lane) * 2);
                #pragma unroll
                for (int x = 0; x < 6; x++)
                    acc2[x] = ffma2(P[2 * x + kx], wp, acc2[x]);
            }
        }
        __syncthreads();    // cur consumers done before it is overwritten
    }

    // ---- bias+relu -> u; partial contraction with dig_W --------------------
    float u[6];
    #pragma unroll
    for (int x = 0; x < 6; x++)
        u[x] = fmaxf(lo32(acc2[x]) + hi32(acc2[x]) + pb, 0.f);

    float part[16];
    #pragma unroll
    for (int e = 0; e < 16; e++) part[e] = 0.f;
    #pragma unroll
    for (int x = 0; x < 6; x++) {
        int n = lane * 36 + x * 6 + r;
        const float4* wv = reinterpret_cast<const float4*>(gdW + n * 128 + d * 16);
        #pragma unroll
        for (int q = 0; q < 4; q++) {
            float4 w4 = wv[q];
            part[q * 4 + 0] += u[x] * w4.x;
            part[q * 4 + 1] += u[x] * w4.y;
            part[q * 4 + 2] += u[x] * w4.z;
            part[q * 4 + 3] += u[x] * w4.w;
        }
    }
    #pragma unroll
    for (int off = 16; off; off >>= 1) {
        #pragma unroll
        for (int e = 0; e < 16; e++)
            part[e] += __shfl_xor_sync(0xffffffffu, part[e], off);
    }

    float* RED = X;           // X slab dead after conv1
    __syncthreads();
    if (lane == 0) {
        #pragma unroll
        for (int e = 0; e < 16; e++) RED[r * 16 + e] = part[e];
    }
    __syncthreads();
    if (r == 0 && lane < 16) {
        float s = 0.f;
        #pragma unroll
        for (int w = 0; w < 6; w++) s += RED[w * 16 + lane];
        g_partial[(bb * 8 + d) * 16 + lane] = s;
    }
}

// ---------------------------------------------------------------------------
__global__ void caps_final(const float* __restrict__ outb, float* __restrict__ out) {
    const int b = blockIdx.x;
    const int lane = threadIdx.x;

    float sb = 0.f;
    if (lane < 16) {
        float s = g_WbSum[lane];
        #pragma unroll
        for (int d = 0; d < 8; d++) s += g_partial[(b * 8 + d) * 16 + lane];
        sb = s * (1.0f / 1152.0f);
    }
    float sq = sb * sb, ab = fabsf(sb);
    #pragma unroll
    for (int off = 16; off; off >>= 1) {
        sq += __shfl_xor_sync(0xffffffffu, sq, off);
        ab += __shfl_xor_sync(0xffffffffu, ab, off);
    }
    float l2 = sqrtf(sq);
    float scale = l2 / ((1.f + l2) * ab);

    __shared__ float vsh[16];
    if (lane < 16) vsh[lane] = sb * scale;
    __syncwarp();

    float logit = -INFINITY;
    if (lane < 10) {
        float L = outb[lane];
        #pragma unroll
        for (int e = 0; e < 16; e++) L += vsh[e] * g_WSum[lane * 16 + e];
        logit = L;
    }
    float m = logit;
    #pragma unroll
    for (int off = 16; off; off >>= 1)
        m = fmaxf(m, __shfl_xor_sync(0xffffffffu, m, off));
    float ex = (lane < 10) ? expf(logit - m) : 0.f;
    float s = ex;
    #pragma unroll
    for (int off = 16; off; off >>= 1)
        s += __shfl_xor_sync(0xffffffffu, s, off);
    if (lane < 10) out[b * 10 + lane] = ex / s;
}

// ---------------------------------------------------------------------------
extern "C" void kernel_launch(void* const* d_in, const int* in_sizes, int n_in,
                              void* d_out, int out_size) {
    const float* x   = (const float*)d_in[0];
    const float* w1  = (const float*)d_in[1];
    const float* b1  = (const float*)d_in[2];
    const float* w2  = (const float*)d_in[3];
    const float* pb  = (const float*)d_in[4];
    const float* dW  = (const float*)d_in[5];
    const float* dWb = (const float*)d_in[6];
    const float* ow  = (const float*)d_in[7];
    const float* ob  = (const float*)d_in[8];
    float* out = (float*)d_out;

    (void)cudaFuncSetAttribute(caps_fused,
                               cudaFuncAttributeMaxDynamicSharedMemorySize,
                               SMEM_BYTES);

    caps_prepW<<<162, 256>>>(w1, w2);
    caps_fused<<<dim3(8, 171), NTHR, SMEM_BYTES>>>(x, b1, pb, dW);
    caps_prepS<<<1, 256>>>(dWb, ow);
    caps_final<<<512, 32>>>(ob, out);
}